// round 15
// baseline (speedup 1.0000x reference)
#include <cuda_runtime.h>
#include <cuda_fp16.h>
#include <cstdint>
#include <cstddef>

// Problem constants
#define B_   32
#define S_   64
#define KX   258        // D_MODEL + 2
#define SA   272        // d_X row stride (floats)
#define H_   256
#define OUT_ 10

// A/activation tile: 128 rows x 336 halfs (168 b32/row; 168%32==8 ->
// LDS.64 phases g0..3 / g4..7 hit banks 8g+2tg, conflict-free)
#define ROW32 168
#define ROWH  336

// dynamic smem byte offsets (k_main)
#define OFF_WB    86016     // A tile: 128*336 halfs
#define OFF_XI    151552    // wbuf: 2 x 32768 B
#define OFF_AIB0  153728
#define OFF_AIB1  154752
#define OFF_B2    155776
#define OFF_B3    156800
#define SMEM_BYTES 157824
#define SMEM_AJI  151552
#define SMEM_MLP  69632

// ---------------- device scratch (static; no allocation) ----------------
__device__ __align__(16) float  d_X[B_ * S_ * SA];
__device__ __align__(16) __half d_Xh[B_ * S_ * 288];   // fragment-permuted fp16 X
__device__ __align__(16) float  d_AJ[B_ * S_ * H_];
__device__ __align__(16) float  d_AI[B_ * S_ * H_];
__device__ __align__(16) float  d_PART[B_ * S_ * H_];
__device__ __align__(16) float  d_S0[B_ * H_];
// weights fp16 in fragment order; 32k-sub-chunk = 8192 halfs; layer1 padded to 320 K
__device__ __align__(16) __half d_WJf[10 * 8192];
__device__ __align__(16) __half d_WIf[10 * 8192];
__device__ __align__(16) __half d_W1f[10 * 8192];
__device__ __align__(16) __half d_W2f[8 * 8192];
__device__ __align__(16) __half d_W3f[8 * 8192];

// ---------------- helpers ----------------
__device__ __forceinline__ void mma16(float (&d)[4], const uint32_t (&a)[4],
                                      const uint32_t (&b)[2]) {
    asm volatile(
        "mma.sync.aligned.m16n8k16.row.col.f32.f16.f16.f32 "
        "{%0,%1,%2,%3}, {%4,%5,%6,%7}, {%8,%9}, {%0,%1,%2,%3};"
        : "+f"(d[0]), "+f"(d[1]), "+f"(d[2]), "+f"(d[3])
        : "r"(a[0]), "r"(a[1]), "r"(a[2]), "r"(a[3]), "r"(b[0]), "r"(b[1]));
}
__device__ __forceinline__ void cpasync16(uint32_t s, const void* g) {
    asm volatile("cp.async.cg.shared.global [%0], [%1], 16;" :: "r"(s), "l"(g));
}
__device__ __forceinline__ uint32_t h2u(__half2 h) {
    return *(uint32_t*)&h;
}

// ---------------- kernel P: prep (X build + X fragments + weight fragments) --
__global__ void __launch_bounds__(256) k_prep(
    const float* __restrict__ sent, const float* __restrict__ coord,
    const float* __restrict__ gw1, const float* __restrict__ gw2,
    const float* __restrict__ gw3)
{
    __shared__ float Ws[32 * 256];
    int blk = blockIdx.x, tid = threadIdx.x;

    if (blk < 32) {
        int r0 = blk * 64;
#pragma unroll 4
        for (int it = 0; it < 17; it++) {
            int s = tid + it * 256;
            int row = s / 68, c4 = s % 68;
            int bs = r0 + row, k = c4 * 4;
            float4 v = make_float4(0.f, 0.f, 0.f, 0.f);
            if (k < 256) v = *(const float4*)(sent + (size_t)bs * 256 + k);
            else if (k == 256) { v.x = coord[(size_t)bs * 2]; v.y = coord[(size_t)bs * 2 + 1]; }
            *(float4*)(d_X + (size_t)bs * SA + k) = v;
        }
        uint32_t* Xh32 = (uint32_t*)d_Xh;
        for (int it = 0; it < 5; it++) {
            int e = tid + it * 256;
            if (e >= 64 * 18) break;
            int row = e / 18, gp = e % 18;
            int bs = r0 + row;
            uint4 u0 = make_uint4(0u, 0u, 0u, 0u), u1 = u0;
            if (gp < 17) {
                float p[16];
                if (gp < 16) {
#pragma unroll
                    for (int t = 0; t < 4; t++) {
                        float4 a = *(const float4*)(sent + (size_t)bs * 256 + gp * 16 + t * 4);
                        p[t*4+0] = a.x; p[t*4+1] = a.y; p[t*4+2] = a.z; p[t*4+3] = a.w;
                    }
                } else {
#pragma unroll
                    for (int t = 0; t < 16; t++) p[t] = 0.f;
                    p[0] = coord[(size_t)bs * 2];
                    p[1] = coord[(size_t)bs * 2 + 1];
                }
                uint32_t wv[8];
#pragma unroll
                for (int pp = 0; pp < 8; pp++) {
                    int kk = 2 * (pp >> 1) + 8 * (pp & 1);
                    wv[pp] = h2u(__floats2half2_rn(p[kk], p[kk + 1]));
                }
                u0 = make_uint4(wv[0], wv[1], wv[2], wv[3]);
                u1 = make_uint4(wv[4], wv[5], wv[6], wv[7]);
            }
            uint4* dst = (uint4*)(Xh32 + (size_t)bs * 144 + gp * 8);
            dst[0] = u0; dst[1] = u1;
        }
    } else {
        int wb = blk - 32;
        const float* gsrc; int rowoff, c, klim; __half* dstf;
        if (wb < 10)      { gsrc = gw1; rowoff = 0;   c = wb;      klim = KX;  dstf = d_WJf; }
        else if (wb < 20) { gsrc = gw1; rowoff = 258; c = wb - 10; klim = KX;  dstf = d_WIf; }
        else if (wb < 30) { gsrc = gw1; rowoff = 516; c = wb - 20; klim = KX;  dstf = d_W1f; }
        else if (wb < 38) { gsrc = gw2; rowoff = 0;   c = wb - 30; klim = 256; dstf = d_W2f; }
        else              { gsrc = gw3; rowoff = 0;   c = wb - 38; klim = 256; dstf = d_W3f; }

#pragma unroll 8
        for (int it = 0; it < 32; it++) {
            int s = tid + it * 256;
            int kk = s >> 8, n = s & 255;
            int k = c * 32 + kk;
            Ws[s] = (k < klim) ? gsrc[(size_t)(rowoff + k) * 256 + n] : 0.f;
        }
        __syncthreads();

        uint4* dst4 = (uint4*)(dstf + (size_t)c * 8192);
#pragma unroll
        for (int it = 0; it < 4; it++) {
            int seg = tid + it * 256;
            __half hv[8];
#pragma unroll
            for (int x = 0; x < 8; x++) {
                int e = seg * 8 + x;
                int off = e >> 1, h = e & 1;
                int ks = off >> 11, rem = off & 2047;
                int nb = rem >> 6, l2 = rem & 63;
                int lane = l2 >> 1, j = l2 & 1;
                int tg = lane & 3, g = lane >> 2;
                int kk = ks * 16 + j * 8 + 2 * tg + h;
                int n = nb * 8 + g;
                hv[x] = __float2half_rn(Ws[kk * 256 + n]);
            }
            uint4 u;
            u.x = h2u(__halves2half2(hv[0], hv[1]));
            u.y = h2u(__halves2half2(hv[2], hv[3]));
            u.z = h2u(__halves2half2(hv[4], hv[5]));
            u.w = h2u(__halves2half2(hv[6], hv[7]));
            dst4[seg] = u;
        }
    }
}

// ---------------- weight chunk staging: linear 32KB copy (256 thr) -----------
__device__ __forceinline__ void stage_chunk(uint32_t bdst, const __half* __restrict__ W) {
    int tid = threadIdx.x;
#pragma unroll
    for (int it = 0; it < 8; it++) {
        int seg = tid + it * 256;
        cpasync16(bdst + (uint32_t)seg * 16u, (const char*)W + (size_t)seg * 16);
    }
    asm volatile("cp.async.commit_group;");
}

// ---------------- fp16 fragment GEMM: 128x256, KC=64, 8 warps, 64x64 tiles ---
__device__ __forceinline__ void gemm_frag(
    float (&acc)[4][8][4],
    const uint32_t* __restrict__ Ap32,
    const uint32_t* __restrict__ wbuf, uint32_t wb_s32,
    const __half* __restrict__ W, int nch, int p0,
    const __half* __restrict__ nextW,
    int wm, int wn, int g, int tg)
{
#pragma unroll
    for (int mi = 0; mi < 4; mi++)
#pragma unroll
        for (int ni = 0; ni < 8; ni++)
#pragma unroll
            for (int q = 0; q < 4; q++) acc[mi][ni][q] = 0.f;

    int lane = threadIdx.x & 31;
    const uint32_t* A0 = Ap32 + (size_t)(wm * 64 + g) * ROW32 + 2 * tg;

    for (int c = 0; c < nch; c++) {
        asm volatile("cp.async.wait_group 0;" ::: "memory");
        __syncthreads();
        if (c + 1 < nch)
            stage_chunk(wb_s32 + (uint32_t)(((c + 1 + p0) & 1)) * 32768u,
                        W + (size_t)(c + 1) * 16384);
        const uint32_t* wb = wbuf + ((c + p0) & 1) * 8192;
#pragma unroll
        for (int ks = 0; ks < 4; ks++) {
            uint32_t a[4][4];
            const uint32_t* ar = A0 + c * 32 + ks * 8;
#pragma unroll
            for (int mi = 0; mi < 4; mi++) {
                uint2 L0 = *(const uint2*)(ar + (size_t)(mi * 16) * ROW32);
                uint2 L1 = *(const uint2*)(ar + (size_t)(mi * 16 + 8) * ROW32);
                a[mi][0] = L0.x; a[mi][1] = L1.x; a[mi][2] = L0.y; a[mi][3] = L1.y;
            }
            const uint32_t* wp = wb + ks * 2048 + wn * 512 + lane * 2;
#pragma unroll
            for (int ni = 0; ni < 8; ni++) {
                uint2 bb = *(const uint2*)(wp + ni * 64);
                uint32_t b[2] = {bb.x, bb.y};
                mma16(acc[0][ni], a[0], b);
                mma16(acc[1][ni], a[1], b);
                mma16(acc[2][ni], a[2], b);
                mma16(acc[3][ni], a[3], b);
            }
        }
    }
    if (nextW)
        stage_chunk(wb_s32 + (uint32_t)(((nch + p0) & 1)) * 32768u, nextW);
}

// ---------------- kernel AJI: AJ/AI via tensor cores, 32 CTAs -----------------
__global__ void __launch_bounds__(256, 1) k_aji() {
    extern __shared__ char smc[];
    uint32_t* Ap32 = (uint32_t*)smc;
    uint32_t* wbuf = (uint32_t*)(smc + OFF_WB);

    int tid = threadIdx.x;
    int w = tid >> 5, lane = tid & 31;
    int wm = w >> 2, wn = w & 3;
    int g = lane >> 2, tg = lane & 3;
    int rb = blockIdx.x >> 1, half_ = blockIdx.x & 1;

    uint32_t a_s32  = (uint32_t)__cvta_generic_to_shared(Ap32);
    uint32_t wb_s32 = (uint32_t)__cvta_generic_to_shared(wbuf);
    const __half* Wf = half_ ? d_WIf : d_WJf;

    // A tile: 128 rows of d_Xh (576 B) into stride-672B rows
#pragma unroll 2
    for (int s = tid; s < 128 * 36; s += 256) {
        int row = s / 36, sg = s % 36;
        cpasync16(a_s32 + (uint32_t)(row * 672 + sg * 16),
                  (const char*)d_Xh + (size_t)(rb * 128 + row) * 576 + sg * 16);
    }
    // zero k-groups 18,19 (b32 144..160) for all 128 rows
    {
        int row = tid >> 1, q4 = (tid & 1) * 2;
        uint4* z = (uint4*)(Ap32 + (size_t)row * ROW32 + 144);
        z[q4] = make_uint4(0u, 0u, 0u, 0u);
        z[q4 + 1] = make_uint4(0u, 0u, 0u, 0u);
    }
    stage_chunk(wb_s32, Wf);

    float acc[4][8][4];
    gemm_frag(acc, Ap32, wbuf, wb_s32, Wf, 5, 0, (const __half*)0, wm, wn, g, tg);

    float* dst = half_ ? d_AI : d_AJ;
#pragma unroll
    for (int mi = 0; mi < 4; mi++) {
        int r = wm * 64 + mi * 16 + g;
#pragma unroll
        for (int ni = 0; ni < 8; ni++) {
            int c0 = wn * 64 + ni * 8 + 2 * tg;
            *(float2*)(dst + (size_t)(rb * 128 + r) * H_ + c0) =
                make_float2(acc[mi][ni][0], acc[mi][ni][1]);
            *(float2*)(dst + (size_t)(rb * 128 + r + 8) * H_ + c0) =
                make_float2(acc[mi][ni][2], acc[mi][ni][3]);
        }
    }
}

// ---------------- kernel C: main fused chain, 256 thr, one CTA per (b,ipair) -
__global__ void __launch_bounds__(256, 1) k_main(
    const float* __restrict__ gb1, const float* __restrict__ gb2,
    const float* __restrict__ gb3)
{
    extern __shared__ char smc[];
    uint32_t* Ap32 = (uint32_t*)smc;
    uint32_t* wbuf = (uint32_t*)(smc + OFF_WB);
    float* xi_s = (float*)(smc + OFF_XI);
    float* aib0 = (float*)(smc + OFF_AIB0);
    float* aib1 = (float*)(smc + OFF_AIB1);
    float* b2s  = (float*)(smc + OFF_B2);
    float* b3s  = (float*)(smc + OFF_B3);

    int tid = threadIdx.x;
    int w = tid >> 5, lane = tid & 31;
    int wm = w >> 2, wn = w & 3;          // warp tile: rows [wm*64,+64), cols [wn*64,+64)
    int g = lane >> 2, tg = lane & 3;
    int b = blockIdx.x >> 5, ip = blockIdx.x & 31;
    int i0 = 2 * ip, i1 = 2 * ip + 1;

    uint32_t wb_s32 = (uint32_t)__cvta_generic_to_shared(wbuf);
    const float* Xb = d_X + (size_t)b * S_ * SA;

    stage_chunk(wb_s32, d_W1f);

    for (int k = tid; k < 2 * SA; k += 256) {
        int half_ = k >= SA, kk = k - half_ * SA;
        xi_s[k] = Xb[(size_t)(half_ ? i1 : i0) * SA + kk];
    }
    aib0[tid] = d_AI[(size_t)(b * S_ + i0) * H_ + tid] + gb1[tid];
    aib1[tid] = d_AI[(size_t)(b * S_ + i1) * H_ + tid] + gb1[tid];
    b2s[tid] = gb2[tid];
    b3s[tid] = gb3[tid];
    __syncthreads();

    // build P tile (half, k-permuted fragment layout), 128 rows x 20 groups
#pragma unroll 1
    for (int q = 0; q < 10; q++) {
        int e = tid + q * 256;              // exactly 2560
        int r = e / 20, gp = e % 20;
        int half_ = r >> 6, j = r & 63;
        uint4 u0 = make_uint4(0u, 0u, 0u, 0u), u1 = u0;
        if (gp < 17) {
            const float* xj = Xb + (size_t)j * SA + gp * 16;
            const float* xv = xi_s + half_ * SA + gp * 16;
            float p[16];
#pragma unroll
            for (int t = 0; t < 4; t++) {
                float4 a = *(const float4*)(xj + t * 4);
                float4 c = *(const float4*)(xv + t * 4);
                p[t*4+0] = a.x * c.x; p[t*4+1] = a.y * c.y;
                p[t*4+2] = a.z * c.z; p[t*4+3] = a.w * c.w;
            }
            uint32_t wv[8];
#pragma unroll
            for (int pp = 0; pp < 8; pp++) {
                int kk = 2 * (pp >> 1) + 8 * (pp & 1);
                wv[pp] = h2u(__floats2half2_rn(p[kk], p[kk + 1]));
            }
            u0 = make_uint4(wv[0], wv[1], wv[2], wv[3]);
            u1 = make_uint4(wv[4], wv[5], wv[6], wv[7]);
        }
        uint4* dst = (uint4*)(Ap32 + (size_t)r * ROW32 + gp * 8);
        dst[0] = u0; dst[1] = u1;
    }

    float acc[4][8][4];

    // ======== layer 1 (K padded to 320 = 5 chunks of 64) ========
    gemm_frag(acc, Ap32, wbuf, wb_s32, d_W1f, 5, 0, d_W2f, wm, wn, g, tg);
    __syncthreads();
    {
        const float* AJb = d_AJ + (size_t)(b * S_) * H_;
        const float* aibp = wm ? aib1 : aib0;
#pragma unroll
        for (int mi = 0; mi < 4; mi++) {
            int r = wm * 64 + mi * 16 + g;
            int j0 = r & 63;
            const float* AJ0 = AJb + (size_t)j0 * H_;
            const float* AJ1 = AJb + (size_t)(j0 + 8) * H_;
#pragma unroll
            for (int ni = 0; ni < 8; ni++) {
                int c0 = wn * 64 + ni * 8 + 2 * tg;
                float2 aj0 = *(const float2*)(AJ0 + c0);
                float2 aj1 = *(const float2*)(AJ1 + c0);
                float2 ab  = *(const float2*)(aibp + c0);
                float v00 = fmaxf(acc[mi][ni][0] + aj0.x + ab.x, 0.f);
                float v01 = fmaxf(acc[mi][ni][1] + aj0.y + ab.y, 0.f);
                float v10 = fmaxf(acc[mi][ni][2] + aj1.x + ab.x, 0.f);
                float v11 = fmaxf(acc[mi][ni][3] + aj1.y + ab.y, 0.f);
                uint32_t boff = (uint32_t)((wn * 4 + (ni >> 1)) * 8 + 2 * tg + (ni & 1));
                Ap32[(size_t)r * ROW32 + boff]       = h2u(__floats2half2_rn(v00, v01));
                Ap32[(size_t)(r + 8) * ROW32 + boff] = h2u(__floats2half2_rn(v10, v11));
            }
        }
    }

    // ======== layer 2 (4 chunks of 64) ========
    gemm_frag(acc, Ap32, wbuf, wb_s32, d_W2f, 4, 1, d_W3f, wm, wn, g, tg);
    __syncthreads();
    {
#pragma unroll
        for (int mi = 0; mi < 4; mi++) {
            int r = wm * 64 + mi * 16 + g;
#pragma unroll
            for (int ni = 0; ni < 8; ni++) {
                int c0 = wn * 64 + ni * 8 + 2 * tg;
                float2 ab = *(const float2*)(b2s + c0);
                float v00 = fmaxf(acc[mi][ni][0] + ab.x, 0.f);
                float v01 = fmaxf(acc[mi][ni][1] + ab.y, 0.f);
                float v10 = fmaxf(acc[mi][ni][2] + ab.x, 0.f);
                float v11 = fmaxf(acc[mi][ni][3] + ab.y, 0.f);
                uint32_t boff = (uint32_t)((wn * 4 + (ni >> 1)) * 8 + 2 * tg + (ni & 1));
                Ap32[(size_t)r * ROW32 + boff]       = h2u(__floats2half2_rn(v00, v01));
                Ap32[(size_t)(r + 8) * ROW32 + boff] = h2u(__floats2half2_rn(v10, v11));
            }
        }
    }

    // ======== layer 3 + row reduction ========
    gemm_frag(acc, Ap32, wbuf, wb_s32, d_W3f, 4, 1, (const __half*)0, wm, wn, g, tg);
    __syncthreads();
    {
#pragma unroll
        for (int mi = 0; mi < 4; mi++) {
            int r = wm * 64 + mi * 16 + g;
#pragma unroll
            for (int ni = 0; ni < 8; ni++) {
                int c0 = wn * 64 + ni * 8 + 2 * tg;
                float2 ab = *(const float2*)(b3s + c0);
                float v00 = fmaxf(acc[mi][ni][0] + ab.x, 0.f);
                float v01 = fmaxf(acc[mi][ni][1] + ab.y, 0.f);
                float v10 = fmaxf(acc[mi][ni][2] + ab.x, 0.f);
                float v11 = fmaxf(acc[mi][ni][3] + ab.y, 0.f);
                Ap32[(size_t)r * ROW32 + (c0 >> 1)]       = h2u(__floats2half2_rn(v00, v01));
                Ap32[(size_t)(r + 8) * ROW32 + (c0 >> 1)] = h2u(__floats2half2_rn(v10, v11));
            }
        }
        __syncthreads();
        const __half* Aph = (const __half*)smc;
        float s0 = 0.f, s1 = 0.f;
#pragma unroll 8
        for (int rr = 0; rr < 64; rr++) {
            s0 += __half2float(Aph[(size_t)rr * ROWH + tid]);
            s1 += __half2float(Aph[(size_t)(64 + rr) * ROWH + tid]);
        }
        d_PART[(size_t)(b * S_ + i0) * H_ + tid] = s0;
        d_PART[(size_t)(b * S_ + i1) * H_ + tid] = s1;
    }
}

// ---------------- kernel R: reduce d_PART over i (parallel, LDG.128) ---------
__global__ void __launch_bounds__(256) k_reduce() {
    __shared__ float4 sm4[256];
    int b = blockIdx.x >> 2, cs = blockIdx.x & 3;
    int t = threadIdx.x, c4 = t & 15, rg = t >> 4;

    const float4* P4 = (const float4*)(d_PART + (size_t)b * S_ * H_) + cs * 16 + c4;
    float4 v0 = P4[(size_t)rg * 64];
    float4 v1 = P4[(size_t)(rg + 16) * 64];
    float4 v2 = P4[(size_t)(rg + 32) * 64];
    float4 v3 = P4[(size_t)(rg + 48) * 64];
    float4 s;
    s.x = (v0.x + v1.x) + (v2.x + v3.x);
    s.y = (v0.y + v1.y) + (v2.y + v3.y);
    s.z = (v0.z + v1.z) + (v2.z + v3.z);
    s.w = (v0.w + v1.w) + (v2.w + v3.w);
    sm4[t] = s;
    __syncthreads();
#pragma unroll
    for (int off = 8; off > 0; off >>= 1) {
        if (rg < off) {
            float4 a = sm4[t], bb = sm4[t + off * 16];
            a.x += bb.x; a.y += bb.y; a.z += bb.z; a.w += bb.w;
            sm4[t] = a;
        }
        __syncthreads();
    }
    if (rg == 0)
        ((float4*)(d_S0 + (size_t)b * H_ + cs * 64))[c4] = sm4[c4];
}

// ---------------- k_mlp: final MLP with cp.async-staged weights --------------
__device__ __forceinline__ void stage_mlp(uint32_t bdst, const float* __restrict__ W) {
    int tid = threadIdx.x;
#pragma unroll
    for (int it = 0; it < 8; it++) {
        int seg = tid + it * 256;
        cpasync16(bdst + (uint32_t)seg * 16u, W + (size_t)seg * 4);
    }
    asm volatile("cp.async.commit_group;");
}

__device__ __forceinline__ float mlp_layer(
    const float* __restrict__ wsm, uint32_t w_s32,
    const float* __restrict__ sin, const float* __restrict__ Wg,
    const float* __restrict__ nextW, int t, int p0)
{
    float a0 = 0.f, a1 = 0.f, a2 = 0.f, a3 = 0.f;
    for (int c = 0; c < 8; c++) {
        asm volatile("cp.async.wait_group 0;" ::: "memory");
        __syncthreads();
        if (c < 7)
            stage_mlp(w_s32 + (uint32_t)(((c + 1 + p0) & 1)) * 32768u,
                      Wg + (size_t)(c + 1) * 8192);
        else if (nextW)
            stage_mlp(w_s32 + (uint32_t)(((8 + p0) & 1)) * 32768u, nextW);
        const float* W = wsm + ((c + p0) & 1) * 8192;
        const float* s = sin + c * 32;
#pragma unroll
        for (int kk = 0; kk < 32; kk += 4) {
            a0 += s[kk]     * W[(kk)     * 256 + t];
            a1 += s[kk + 1] * W[(kk + 1) * 256 + t];
            a2 += s[kk + 2] * W[(kk + 2) * 256 + t];
            a3 += s[kk + 3] * W[(kk + 3) * 256 + t];
        }
    }
    return (a0 + a1) + (a2 + a3);
}

__global__ void __launch_bounds__(256) k_mlp(
    const float* __restrict__ fw1, const float* __restrict__ fb1,
    const float* __restrict__ fw2, const float* __restrict__ fb2,
    const float* __restrict__ fw3, const float* __restrict__ fb3,
    float* __restrict__ out)
{
    extern __shared__ char smc[];
    float* wsm = (float*)smc;
    float* s0  = (float*)(smc + 65536);
    float* s1  = s0 + 256;
    float* s2  = s1 + 256;
    float* pp  = s2 + 256;

    int b = blockIdx.x, t = threadIdx.x;
    uint32_t w_s32 = (uint32_t)__cvta_generic_to_shared(wsm);

    stage_mlp(w_s32, fw1);
    s0[t] = d_S0[(size_t)b * H_ + t];
    float r1 = mlp_layer(wsm, w_s32, s0, fw1, fw2, t, 0);
    s1[t] = fmaxf(r1 + fb1[t], 0.f);
    float r2 = mlp_layer(wsm, w_s32, s1, fw2, (const float*)0, t, 0);
    s2[t] = fmaxf(r2 + fb2[t], 0.f);

    for (int seg = t; seg < 640; seg += 256)
        cpasync16(w_s32 + (uint32_t)seg * 16u, fw3 + (size_t)seg * 4);
    asm volatile("cp.async.commit_group;");
    asm volatile("cp.async.wait_group 0;" ::: "memory");
    __syncthreads();

    if (t < 160) {
        int o = t % 10, h = t / 10;
        float a = 0.f;
#pragma unroll
        for (int k = 0; k < 16; k++)
            a += s2[h * 16 + k] * wsm[(h * 16 + k) * 10 + o];
        pp[t] = a;
    }
    __syncthreads();
    if (t < OUT_) {
        float a = fb3[t];
#pragma unroll
        for (int h = 0; h < 16; h++) a += pp[h * 10 + t];
        out[b * OUT_ + t] = a;
    }
}

// ---------------- launch ----------------
extern "C" void kernel_launch(void* const* d_in, const int* in_sizes, int n_in,
                              void* d_out, int out_size) {
    const float* sent  = (const float*)d_in[0];
    const float* coord = (const float*)d_in[1];
    const float* gw1   = (const float*)d_in[2];
    const float* gb1   = (const float*)d_in[3];
    const float* gw2   = (const float*)d_in[4];
    const float* gb2   = (const float*)d_in[5];
    const float* gw3   = (const float*)d_in[6];
    const float* gb3   = (const float*)d_in[7];
    const float* fw1   = (const float*)d_in[8];
    const float* fb1   = (const float*)d_in[9];
    const float* fw2   = (const float*)d_in[10];
    const float* fb2   = (const float*)d_in[11];
    const float* fw3   = (const float*)d_in[12];
    const float* fb3   = (const float*)d_in[13];
    float* out = (float*)d_out;

    k_prep<<<78, 256>>>(sent, coord, gw1, gw2, gw3);

    cudaFuncSetAttribute(k_aji, cudaFuncAttributeMaxDynamicSharedMemorySize,
                         SMEM_AJI);
    k_aji<<<32, 256, SMEM_AJI>>>();

    cudaFuncSetAttribute(k_main, cudaFuncAttributeMaxDynamicSharedMemorySize,
                         SMEM_BYTES);
    k_main<<<B_ * S_ / 2, 256, SMEM_BYTES>>>(gb1, gb2, gb3);

    k_reduce<<<B_ * 4, 256>>>();

    cudaFuncSetAttribute(k_mlp, cudaFuncAttributeMaxDynamicSharedMemorySize,
                         SMEM_MLP);
    k_mlp<<<B_, 256, SMEM_MLP>>>(fw1, fb1, fw2, fb2, fw3, fb3, out);
}

// round 16
// speedup vs baseline: 1.0106x; 1.0106x over previous
#include <cuda_runtime.h>
#include <cuda_fp16.h>
#include <cstdint>
#include <cstddef>

// Problem constants
#define B_   32
#define S_   64
#define KX   258        // D_MODEL + 2
#define SA   272        // d_X row stride (floats)
#define H_   256
#define OUT_ 10

// A/activation tile: 128 rows x 336 halfs (168 b32/row; 168%32==8 ->
// LDS.64 phases g0..3 / g4..7 hit banks 8g+2tg, conflict-free)
#define ROW32 168
#define ROWH  336

// dynamic smem byte offsets (k_main)
#define OFF_WB    86016     // A tile: 128*336 halfs
#define OFF_XI    151552    // wbuf: 2 x 32768 B
#define OFF_AIB0  153728
#define OFF_AIB1  154752
#define OFF_B2    155776
#define OFF_B3    156800
#define SMEM_BYTES 157824
#define SMEM_AJI  151552
#define SMEM_MLP  69632

// ---------------- device scratch (static; no allocation) ----------------
__device__ __align__(16) float  d_X[B_ * S_ * SA];
__device__ __align__(16) __half d_Xh[B_ * S_ * 288];   // fragment-permuted fp16 X
__device__ __align__(16) float  d_AJ[B_ * S_ * H_];
__device__ __align__(16) float  d_AI[B_ * S_ * H_];
__device__ __align__(16) float  d_PART[B_ * S_ * H_];
// weights fp16 in fragment order; 32k-sub-chunk = 8192 halfs; layer1 padded to 320 K
__device__ __align__(16) __half d_WJf[10 * 8192];
__device__ __align__(16) __half d_WIf[10 * 8192];
__device__ __align__(16) __half d_W1f[10 * 8192];
__device__ __align__(16) __half d_W2f[8 * 8192];
__device__ __align__(16) __half d_W3f[8 * 8192];

// ---------------- helpers ----------------
__device__ __forceinline__ void mma16(float (&d)[4], const uint32_t (&a)[4],
                                      const uint32_t (&b)[2]) {
    asm volatile(
        "mma.sync.aligned.m16n8k16.row.col.f32.f16.f16.f32 "
        "{%0,%1,%2,%3}, {%4,%5,%6,%7}, {%8,%9}, {%0,%1,%2,%3};"
        : "+f"(d[0]), "+f"(d[1]), "+f"(d[2]), "+f"(d[3])
        : "r"(a[0]), "r"(a[1]), "r"(a[2]), "r"(a[3]), "r"(b[0]), "r"(b[1]));
}
__device__ __forceinline__ void cpasync16(uint32_t s, const void* g) {
    asm volatile("cp.async.cg.shared.global [%0], [%1], 16;" :: "r"(s), "l"(g));
}
__device__ __forceinline__ uint32_t h2u(__half2 h) {
    return *(uint32_t*)&h;
}

// ---------------- kernel P: prep (X build + X fragments + weight fragments) --
__global__ void __launch_bounds__(256) k_prep(
    const float* __restrict__ sent, const float* __restrict__ coord,
    const float* __restrict__ gw1, const float* __restrict__ gw2,
    const float* __restrict__ gw3)
{
    __shared__ float Ws[32 * 256];
    int blk = blockIdx.x, tid = threadIdx.x;

    if (blk < 32) {
        int r0 = blk * 64;
#pragma unroll 4
        for (int it = 0; it < 17; it++) {
            int s = tid + it * 256;
            int row = s / 68, c4 = s % 68;
            int bs = r0 + row, k = c4 * 4;
            float4 v = make_float4(0.f, 0.f, 0.f, 0.f);
            if (k < 256) v = *(const float4*)(sent + (size_t)bs * 256 + k);
            else if (k == 256) { v.x = coord[(size_t)bs * 2]; v.y = coord[(size_t)bs * 2 + 1]; }
            *(float4*)(d_X + (size_t)bs * SA + k) = v;
        }
        uint32_t* Xh32 = (uint32_t*)d_Xh;
        for (int it = 0; it < 5; it++) {
            int e = tid + it * 256;
            if (e >= 64 * 18) break;
            int row = e / 18, gp = e % 18;
            int bs = r0 + row;
            uint4 u0 = make_uint4(0u, 0u, 0u, 0u), u1 = u0;
            if (gp < 17) {
                float p[16];
                if (gp < 16) {
#pragma unroll
                    for (int t = 0; t < 4; t++) {
                        float4 a = *(const float4*)(sent + (size_t)bs * 256 + gp * 16 + t * 4);
                        p[t*4+0] = a.x; p[t*4+1] = a.y; p[t*4+2] = a.z; p[t*4+3] = a.w;
                    }
                } else {
#pragma unroll
                    for (int t = 0; t < 16; t++) p[t] = 0.f;
                    p[0] = coord[(size_t)bs * 2];
                    p[1] = coord[(size_t)bs * 2 + 1];
                }
                uint32_t wv[8];
#pragma unroll
                for (int pp = 0; pp < 8; pp++) {
                    int kk = 2 * (pp >> 1) + 8 * (pp & 1);
                    wv[pp] = h2u(__floats2half2_rn(p[kk], p[kk + 1]));
                }
                u0 = make_uint4(wv[0], wv[1], wv[2], wv[3]);
                u1 = make_uint4(wv[4], wv[5], wv[6], wv[7]);
            }
            uint4* dst = (uint4*)(Xh32 + (size_t)bs * 144 + gp * 8);
            dst[0] = u0; dst[1] = u1;
        }
    } else {
        int wb = blk - 32;
        const float* gsrc; int rowoff, c, klim; __half* dstf;
        if (wb < 10)      { gsrc = gw1; rowoff = 0;   c = wb;      klim = KX;  dstf = d_WJf; }
        else if (wb < 20) { gsrc = gw1; rowoff = 258; c = wb - 10; klim = KX;  dstf = d_WIf; }
        else if (wb < 30) { gsrc = gw1; rowoff = 516; c = wb - 20; klim = KX;  dstf = d_W1f; }
        else if (wb < 38) { gsrc = gw2; rowoff = 0;   c = wb - 30; klim = 256; dstf = d_W2f; }
        else              { gsrc = gw3; rowoff = 0;   c = wb - 38; klim = 256; dstf = d_W3f; }

#pragma unroll 8
        for (int it = 0; it < 32; it++) {
            int s = tid + it * 256;
            int kk = s >> 8, n = s & 255;
            int k = c * 32 + kk;
            Ws[s] = (k < klim) ? gsrc[(size_t)(rowoff + k) * 256 + n] : 0.f;
        }
        __syncthreads();

        uint4* dst4 = (uint4*)(dstf + (size_t)c * 8192);
#pragma unroll
        for (int it = 0; it < 4; it++) {
            int seg = tid + it * 256;
            __half hv[8];
#pragma unroll
            for (int x = 0; x < 8; x++) {
                int e = seg * 8 + x;
                int off = e >> 1, h = e & 1;
                int ks = off >> 11, rem = off & 2047;
                int nb = rem >> 6, l2 = rem & 63;
                int lane = l2 >> 1, j = l2 & 1;
                int tg = lane & 3, g = lane >> 2;
                int kk = ks * 16 + j * 8 + 2 * tg + h;
                int n = nb * 8 + g;
                hv[x] = __float2half_rn(Ws[kk * 256 + n]);
            }
            uint4 u;
            u.x = h2u(__halves2half2(hv[0], hv[1]));
            u.y = h2u(__halves2half2(hv[2], hv[3]));
            u.z = h2u(__halves2half2(hv[4], hv[5]));
            u.w = h2u(__halves2half2(hv[6], hv[7]));
            dst4[seg] = u;
        }
    }
}

// ---------------- weight chunk staging: linear 32KB copy (512 thr) -----------
__device__ __forceinline__ void stage_chunk(uint32_t bdst, const __half* __restrict__ W) {
    int tid = threadIdx.x;
#pragma unroll
    for (int it = 0; it < 4; it++) {
        int seg = tid + it * 512;
        cpasync16(bdst + (uint32_t)seg * 16u, (const char*)W + (size_t)seg * 16);
    }
    asm volatile("cp.async.commit_group;");
}

// ---------------- fp16 fragment GEMM: 128x256, KC=64, 16 warps ---------------
__device__ __forceinline__ void gemm_frag(
    float (&acc)[2][8][4],
    const uint32_t* __restrict__ Ap32,
    const uint32_t* __restrict__ wbuf, uint32_t wb_s32,
    const __half* __restrict__ W, int nch, int p0,
    const __half* __restrict__ nextW,
    int wm, int wn, int g, int tg)
{
#pragma unroll
    for (int mi = 0; mi < 2; mi++)
#pragma unroll
        for (int ni = 0; ni < 8; ni++)
#pragma unroll
            for (int q = 0; q < 4; q++) acc[mi][ni][q] = 0.f;

    int lane = threadIdx.x & 31;
    const uint32_t* A0 = Ap32 + (size_t)(wm * 32 + g) * ROW32 + 2 * tg;

    for (int c = 0; c < nch; c++) {
        asm volatile("cp.async.wait_group 0;" ::: "memory");
        __syncthreads();
        if (c + 1 < nch)
            stage_chunk(wb_s32 + (uint32_t)(((c + 1 + p0) & 1)) * 32768u,
                        W + (size_t)(c + 1) * 16384);
        const uint32_t* wb = wbuf + ((c + p0) & 1) * 8192;
#pragma unroll
        for (int ks = 0; ks < 4; ks++) {
            uint32_t a[2][4];
            const uint32_t* ar = A0 + c * 32 + ks * 8;
#pragma unroll
            for (int mi = 0; mi < 2; mi++) {
                uint2 L0 = *(const uint2*)(ar + (size_t)(mi * 16) * ROW32);
                uint2 L1 = *(const uint2*)(ar + (size_t)(mi * 16 + 8) * ROW32);
                a[mi][0] = L0.x; a[mi][1] = L1.x; a[mi][2] = L0.y; a[mi][3] = L1.y;
            }
            const uint32_t* wp = wb + ks * 2048 + wn * 512 + lane * 2;
#pragma unroll
            for (int ni = 0; ni < 8; ni++) {
                uint2 bb = *(const uint2*)(wp + ni * 64);
                uint32_t b[2] = {bb.x, bb.y};
                mma16(acc[0][ni], a[0], b);
                mma16(acc[1][ni], a[1], b);
            }
        }
    }
    if (nextW)
        stage_chunk(wb_s32 + (uint32_t)(((nch + p0) & 1)) * 32768u, nextW);
}

// ---------------- kernel AJI: AJ/AI via tensor cores, 32 CTAs -----------------
__global__ void __launch_bounds__(512, 1) k_aji() {
    extern __shared__ char smc[];
    uint32_t* Ap32 = (uint32_t*)smc;
    uint32_t* wbuf = (uint32_t*)(smc + OFF_WB);

    int tid = threadIdx.x;
    int w = tid >> 5, lane = tid & 31;
    int wm = w >> 2, wn = w & 3;
    int g = lane >> 2, tg = lane & 3;
    int rb = blockIdx.x >> 1, half_ = blockIdx.x & 1;

    uint32_t a_s32  = (uint32_t)__cvta_generic_to_shared(Ap32);
    uint32_t wb_s32 = (uint32_t)__cvta_generic_to_shared(wbuf);
    const __half* Wf = half_ ? d_WIf : d_WJf;

    // A tile: 128 rows of d_Xh (576 B) into stride-672B rows; zero groups 18,19
#pragma unroll 2
    for (int s = tid; s < 128 * 36; s += 512) {
        int row = s / 36, sg = s % 36;
        cpasync16(a_s32 + (uint32_t)(row * 672 + sg * 16),
                  (const char*)d_Xh + (size_t)(rb * 128 + row) * 576 + sg * 16);
    }
    {
        int row = tid >> 2, q4 = tid & 3;
        ((uint4*)(Ap32 + (size_t)row * ROW32 + 144))[q4] = make_uint4(0u, 0u, 0u, 0u);
    }
    stage_chunk(wb_s32, Wf);

    float acc[2][8][4];
    gemm_frag(acc, Ap32, wbuf, wb_s32, Wf, 5, 0, (const __half*)0, wm, wn, g, tg);

    float* dst = half_ ? d_AI : d_AJ;
#pragma unroll
    for (int mi = 0; mi < 2; mi++) {
        int r = wm * 32 + mi * 16 + g;
#pragma unroll
        for (int ni = 0; ni < 8; ni++) {
            int c0 = wn * 64 + ni * 8 + 2 * tg;
            *(float2*)(dst + (size_t)(rb * 128 + r) * H_ + c0) =
                make_float2(acc[mi][ni][0], acc[mi][ni][1]);
            *(float2*)(dst + (size_t)(rb * 128 + r + 8) * H_ + c0) =
                make_float2(acc[mi][ni][2], acc[mi][ni][3]);
        }
    }
}

// ---------------- kernel C: main fused chain, 512 thr, one CTA per (b,ipair) -
__global__ void __launch_bounds__(512, 1) k_main(
    const float* __restrict__ gb1, const float* __restrict__ gb2,
    const float* __restrict__ gb3)
{
    extern __shared__ char smc[];
    uint32_t* Ap32 = (uint32_t*)smc;
    uint32_t* wbuf = (uint32_t*)(smc + OFF_WB);
    float* xi_s = (float*)(smc + OFF_XI);
    float* aib0 = (float*)(smc + OFF_AIB0);
    float* aib1 = (float*)(smc + OFF_AIB1);
    float* b2s  = (float*)(smc + OFF_B2);
    float* b3s  = (float*)(smc + OFF_B3);

    int tid = threadIdx.x;
    int w = tid >> 5, lane = tid & 31;
    int wm = w >> 2, wn = w & 3;
    int g = lane >> 2, tg = lane & 3;
    int b = blockIdx.x >> 5, ip = blockIdx.x & 31;
    int i0 = 2 * ip, i1 = 2 * ip + 1;

    uint32_t wb_s32 = (uint32_t)__cvta_generic_to_shared(wbuf);
    const float* Xb = d_X + (size_t)b * S_ * SA;

    stage_chunk(wb_s32, d_W1f);

    for (int k = tid; k < 2 * SA; k += 512) {
        int half_ = k >= SA, kk = k - half_ * SA;
        xi_s[k] = Xb[(size_t)(half_ ? i1 : i0) * SA + kk];
    }
    if (tid < 256) {
        aib0[tid] = d_AI[(size_t)(b * S_ + i0) * H_ + tid] + gb1[tid];
        aib1[tid] = d_AI[(size_t)(b * S_ + i1) * H_ + tid] + gb1[tid];
        b2s[tid] = gb2[tid];
        b3s[tid] = gb3[tid];
    }
    __syncthreads();

    // build P tile (half, k-permuted fragment layout), 128 rows x 20 groups
#pragma unroll 1
    for (int q = 0; q < 5; q++) {
        int e = tid + q * 512;              // exactly 2560
        int r = e / 20, gp = e % 20;
        int half_ = r >> 6, j = r & 63;
        uint4 u0 = make_uint4(0u, 0u, 0u, 0u), u1 = u0;
        if (gp < 17) {
            const float* xj = Xb + (size_t)j * SA + gp * 16;
            const float* xv = xi_s + half_ * SA + gp * 16;
            float p[16];
#pragma unroll
            for (int t = 0; t < 4; t++) {
                float4 a = *(const float4*)(xj + t * 4);
                float4 c = *(const float4*)(xv + t * 4);
                p[t*4+0] = a.x * c.x; p[t*4+1] = a.y * c.y;
                p[t*4+2] = a.z * c.z; p[t*4+3] = a.w * c.w;
            }
            uint32_t wv[8];
#pragma unroll
            for (int pp = 0; pp < 8; pp++) {
                int kk = 2 * (pp >> 1) + 8 * (pp & 1);
                wv[pp] = h2u(__floats2half2_rn(p[kk], p[kk + 1]));
            }
            u0 = make_uint4(wv[0], wv[1], wv[2], wv[3]);
            u1 = make_uint4(wv[4], wv[5], wv[6], wv[7]);
        }
        uint4* dst = (uint4*)(Ap32 + (size_t)r * ROW32 + gp * 8);
        dst[0] = u0; dst[1] = u1;
    }

    float acc[2][8][4];

    // ======== layer 1 (K padded to 320 = 5 chunks of 64) ========
    gemm_frag(acc, Ap32, wbuf, wb_s32, d_W1f, 5, 0, d_W2f, wm, wn, g, tg);
    __syncthreads();
    {
        const float* AJb = d_AJ + (size_t)(b * S_) * H_;
        const float* aibp = (wm >= 2) ? aib1 : aib0;
#pragma unroll
        for (int mi = 0; mi < 2; mi++) {
            int r = wm * 32 + mi * 16 + g;
            int j0 = r & 63;
            const float* AJ0 = AJb + (size_t)j0 * H_;
            const float* AJ1 = AJb + (size_t)(j0 + 8) * H_;
#pragma unroll
            for (int ni = 0; ni < 8; ni++) {
                int c0 = wn * 64 + ni * 8 + 2 * tg;
                float2 aj0 = *(const float2*)(AJ0 + c0);
                float2 aj1 = *(const float2*)(AJ1 + c0);
                float2 ab  = *(const float2*)(aibp + c0);
                float v00 = fmaxf(acc[mi][ni][0] + aj0.x + ab.x, 0.f);
                float v01 = fmaxf(acc[mi][ni][1] + aj0.y + ab.y, 0.f);
                float v10 = fmaxf(acc[mi][ni][2] + aj1.x + ab.x, 0.f);
                float v11 = fmaxf(acc[mi][ni][3] + aj1.y + ab.y, 0.f);
                uint32_t boff = (uint32_t)((wn * 4 + (ni >> 1)) * 8 + 2 * tg + (ni & 1));
                Ap32[(size_t)r * ROW32 + boff]       = h2u(__floats2half2_rn(v00, v01));
                Ap32[(size_t)(r + 8) * ROW32 + boff] = h2u(__floats2half2_rn(v10, v11));
            }
        }
    }

    // ======== layer 2 (4 chunks of 64) ========
    gemm_frag(acc, Ap32, wbuf, wb_s32, d_W2f, 4, 1, d_W3f, wm, wn, g, tg);
    __syncthreads();
    {
#pragma unroll
        for (int mi = 0; mi < 2; mi++) {
            int r = wm * 32 + mi * 16 + g;
#pragma unroll
            for (int ni = 0; ni < 8; ni++) {
                int c0 = wn * 64 + ni * 8 + 2 * tg;
                float2 ab = *(const float2*)(b2s + c0);
                float v00 = fmaxf(acc[mi][ni][0] + ab.x, 0.f);
                float v01 = fmaxf(acc[mi][ni][1] + ab.y, 0.f);
                float v10 = fmaxf(acc[mi][ni][2] + ab.x, 0.f);
                float v11 = fmaxf(acc[mi][ni][3] + ab.y, 0.f);
                uint32_t boff = (uint32_t)((wn * 4 + (ni >> 1)) * 8 + 2 * tg + (ni & 1));
                Ap32[(size_t)r * ROW32 + boff]       = h2u(__floats2half2_rn(v00, v01));
                Ap32[(size_t)(r + 8) * ROW32 + boff] = h2u(__floats2half2_rn(v10, v11));
            }
        }
    }

    // ======== layer 3 + row reduction ========
    gemm_frag(acc, Ap32, wbuf, wb_s32, d_W3f, 4, 1, (const __half*)0, wm, wn, g, tg);
    __syncthreads();
    {
#pragma unroll
        for (int mi = 0; mi < 2; mi++) {
            int r = wm * 32 + mi * 16 + g;
#pragma unroll
            for (int ni = 0; ni < 8; ni++) {
                int c0 = wn * 64 + ni * 8 + 2 * tg;
                float2 ab = *(const float2*)(b3s + c0);
                float v00 = fmaxf(acc[mi][ni][0] + ab.x, 0.f);
                float v01 = fmaxf(acc[mi][ni][1] + ab.y, 0.f);
                float v10 = fmaxf(acc[mi][ni][2] + ab.x, 0.f);
                float v11 = fmaxf(acc[mi][ni][3] + ab.y, 0.f);
                Ap32[(size_t)r * ROW32 + (c0 >> 1)]       = h2u(__floats2half2_rn(v00, v01));
                Ap32[(size_t)(r + 8) * ROW32 + (c0 >> 1)] = h2u(__floats2half2_rn(v10, v11));
            }
        }
        __syncthreads();
        const __half* Aph = (const __half*)smc;
        int t = tid & 255, h = tid >> 8;
        float s = 0.f;
#pragma unroll 8
        for (int rr = 0; rr < 64; rr++)
            s += __half2float(Aph[(size_t)(h * 64 + rr) * ROWH + t]);
        d_PART[(size_t)(b * S_ + (h ? i1 : i0)) * H_ + t] = s;
    }
}

// ---------------- k_mlp: PART reduction + final MLP (merged) -----------------
__device__ __forceinline__ void stage_mlp(uint32_t bdst, const float* __restrict__ W) {
    int tid = threadIdx.x;
#pragma unroll
    for (int it = 0; it < 8; it++) {
        int seg = tid + it * 256;
        cpasync16(bdst + (uint32_t)seg * 16u, W + (size_t)seg * 4);
    }
    asm volatile("cp.async.commit_group;");
}

__device__ __forceinline__ float mlp_layer(
    const float* __restrict__ wsm, uint32_t w_s32,
    const float* __restrict__ sin, const float* __restrict__ Wg,
    const float* __restrict__ nextW, int t, int p0)
{
    float a0 = 0.f, a1 = 0.f, a2 = 0.f, a3 = 0.f;
    for (int c = 0; c < 8; c++) {
        asm volatile("cp.async.wait_group 0;" ::: "memory");
        __syncthreads();
        if (c < 7)
            stage_mlp(w_s32 + (uint32_t)(((c + 1 + p0) & 1)) * 32768u,
                      Wg + (size_t)(c + 1) * 8192);
        else if (nextW)
            stage_mlp(w_s32 + (uint32_t)(((8 + p0) & 1)) * 32768u, nextW);
        const float* W = wsm + ((c + p0) & 1) * 8192;
        const float* s = sin + c * 32;
#pragma unroll
        for (int kk = 0; kk < 32; kk += 4) {
            a0 += s[kk]     * W[(kk)     * 256 + t];
            a1 += s[kk + 1] * W[(kk + 1) * 256 + t];
            a2 += s[kk + 2] * W[(kk + 2) * 256 + t];
            a3 += s[kk + 3] * W[(kk + 3) * 256 + t];
        }
    }
    return (a0 + a1) + (a2 + a3);
}

__global__ void __launch_bounds__(256) k_mlp(
    const float* __restrict__ fw1, const float* __restrict__ fb1,
    const float* __restrict__ fw2, const float* __restrict__ fb2,
    const float* __restrict__ fw3, const float* __restrict__ fb3,
    float* __restrict__ out)
{
    extern __shared__ char smc[];
    float* wsm = (float*)smc;
    float* s0  = (float*)(smc + 65536);
    float* s1  = s0 + 256;
    float* s2  = s1 + 256;
    float* pp  = s2 + 256;

    int b = blockIdx.x, t = threadIdx.x;
    uint32_t w_s32 = (uint32_t)__cvta_generic_to_shared(wsm);

    stage_mlp(w_s32, fw1);   // fw1 chunk 0 loads while we reduce PART

    // reduce d_PART over i (64 rows), coalesced, overlapped with the cp.async
    {
        const float* P = d_PART + (size_t)b * S_ * H_ + t;
        float s = 0.f;
#pragma unroll 8
        for (int i = 0; i < S_; i++) s += P[(size_t)i * H_];
        s0[t] = s;   // visibility covered by mlp_layer's first wait+sync
    }

    float r1 = mlp_layer(wsm, w_s32, s0, fw1, fw2, t, 0);
    s1[t] = fmaxf(r1 + fb1[t], 0.f);
    float r2 = mlp_layer(wsm, w_s32, s1, fw2, (const float*)0, t, 0);
    s2[t] = fmaxf(r2 + fb2[t], 0.f);

    for (int seg = t; seg < 640; seg += 256)
        cpasync16(w_s32 + (uint32_t)seg * 16u, fw3 + (size_t)seg * 4);
    asm volatile("cp.async.commit_group;");
    asm volatile("cp.async.wait_group 0;" ::: "memory");
    __syncthreads();

    if (t < 160) {
        int o = t % 10, h = t / 10;
        float a = 0.f;
#pragma unroll
        for (int k = 0; k < 16; k++)
            a += s2[h * 16 + k] * wsm[(h * 16 + k) * 10 + o];
        pp[t] = a;
    }
    __syncthreads();
    if (t < OUT_) {
        float a = fb3[t];
#pragma unroll
        for (int h = 0; h < 16; h++) a += pp[h * 10 + t];
        out[b * OUT_ + t] = a;
    }
}

// ---------------- launch ----------------
extern "C" void kernel_launch(void* const* d_in, const int* in_sizes, int n_in,
                              void* d_out, int out_size) {
    const float* sent  = (const float*)d_in[0];
    const float* coord = (const float*)d_in[1];
    const float* gw1   = (const float*)d_in[2];
    const float* gb1   = (const float*)d_in[3];
    const float* gw2   = (const float*)d_in[4];
    const float* gb2   = (const float*)d_in[5];
    const float* gw3   = (const float*)d_in[6];
    const float* gb3   = (const float*)d_in[7];
    const float* fw1   = (const float*)d_in[8];
    const float* fb1   = (const float*)d_in[9];
    const float* fw2   = (const float*)d_in[10];
    const float* fb2   = (const float*)d_in[11];
    const float* fw3   = (const float*)d_in[12];
    const float* fb3   = (const float*)d_in[13];
    float* out = (float*)d_out;

    k_prep<<<78, 256>>>(sent, coord, gw1, gw2, gw3);

    cudaFuncSetAttribute(k_aji, cudaFuncAttributeMaxDynamicSharedMemorySize,
                         SMEM_AJI);
    k_aji<<<32, 512, SMEM_AJI>>>();

    cudaFuncSetAttribute(k_main, cudaFuncAttributeMaxDynamicSharedMemorySize,
                         SMEM_BYTES);
    k_main<<<B_ * S_ / 2, 512, SMEM_BYTES>>>(gb1, gb2, gb3);

    cudaFuncSetAttribute(k_mlp, cudaFuncAttributeMaxDynamicSharedMemorySize,
                         SMEM_MLP);
    k_mlp<<<B_, 256, SMEM_MLP>>>(fw1, fb1, fw2, fb2, fw3, fb3, out);
}

// round 17
// speedup vs baseline: 1.0553x; 1.0442x over previous
#include <cuda_runtime.h>
#include <cuda_fp16.h>
#include <cstdint>
#include <cstddef>

// Problem constants
#define B_   32
#define S_   64
#define KX   258        // D_MODEL + 2
#define SA   272        // d_X row stride (floats)
#define H_   256
#define OUT_ 10

// A/activation tile: 128 rows x 336 halfs (168 b32/row)
#define ROW32 168
#define ROWH  336

// dynamic smem byte offsets (k_main)
#define OFF_WB    86016     // A tile: 128*336 halfs
#define OFF_XI    151552    // wbuf: 2 x 32768 B
#define OFF_AIB0  153728
#define OFF_AIB1  154752
#define OFF_B2    155776
#define OFF_B3    156800
#define SMEM_BYTES 157824
#define SMEM_AJI  151552
#define SMEM_MLP  103424    // 3 x 32768 wbuf + s0/s1/s2 + pp

// ---------------- device scratch (static; no allocation) ----------------
__device__ __align__(16) float  d_X[B_ * S_ * SA];
__device__ __align__(16) __half d_Xh[B_ * S_ * 288];   // fragment-permuted fp16 X
__device__ __align__(16) float  d_AJ[B_ * S_ * H_];
__device__ __align__(16) float  d_AI[B_ * S_ * H_];
__device__ __align__(16) float  d_PART[B_ * S_ * H_];
// weights fp16 in fragment order; 32k-sub-chunk = 8192 halfs; layer1 padded to 320 K
__device__ __align__(16) __half d_WJf[10 * 8192];
__device__ __align__(16) __half d_WIf[10 * 8192];
__device__ __align__(16) __half d_W1f[10 * 8192];
__device__ __align__(16) __half d_W2f[8 * 8192];
__device__ __align__(16) __half d_W3f[8 * 8192];

// ---------------- helpers ----------------
__device__ __forceinline__ void mma16(float (&d)[4], const uint32_t (&a)[4],
                                      const uint32_t (&b)[2]) {
    asm volatile(
        "mma.sync.aligned.m16n8k16.row.col.f32.f16.f16.f32 "
        "{%0,%1,%2,%3}, {%4,%5,%6,%7}, {%8,%9}, {%0,%1,%2,%3};"
        : "+f"(d[0]), "+f"(d[1]), "+f"(d[2]), "+f"(d[3])
        : "r"(a[0]), "r"(a[1]), "r"(a[2]), "r"(a[3]), "r"(b[0]), "r"(b[1]));
}
__device__ __forceinline__ void cpasync16(uint32_t s, const void* g) {
    asm volatile("cp.async.cg.shared.global [%0], [%1], 16;" :: "r"(s), "l"(g));
}
__device__ __forceinline__ uint32_t h2u(__half2 h) {
    return *(uint32_t*)&h;
}

// ---------------- kernel P: prep (X build + X fragments + weight fragments) --
__global__ void __launch_bounds__(256) k_prep(
    const float* __restrict__ sent, const float* __restrict__ coord,
    const float* __restrict__ gw1, const float* __restrict__ gw2,
    const float* __restrict__ gw3)
{
    __shared__ float Ws[32 * 256];
    int blk = blockIdx.x, tid = threadIdx.x;

    if (blk < 32) {
        int r0 = blk * 64;
#pragma unroll 4
        for (int it = 0; it < 17; it++) {
            int s = tid + it * 256;
            int row = s / 68, c4 = s % 68;
            int bs = r0 + row, k = c4 * 4;
            float4 v = make_float4(0.f, 0.f, 0.f, 0.f);
            if (k < 256) v = *(const float4*)(sent + (size_t)bs * 256 + k);
            else if (k == 256) { v.x = coord[(size_t)bs * 2]; v.y = coord[(size_t)bs * 2 + 1]; }
            *(float4*)(d_X + (size_t)bs * SA + k) = v;
        }
        uint32_t* Xh32 = (uint32_t*)d_Xh;
        for (int it = 0; it < 5; it++) {
            int e = tid + it * 256;
            if (e >= 64 * 18) break;
            int row = e / 18, gp = e % 18;
            int bs = r0 + row;
            uint4 u0 = make_uint4(0u, 0u, 0u, 0u), u1 = u0;
            if (gp < 17) {
                float p[16];
                if (gp < 16) {
#pragma unroll
                    for (int t = 0; t < 4; t++) {
                        float4 a = *(const float4*)(sent + (size_t)bs * 256 + gp * 16 + t * 4);
                        p[t*4+0] = a.x; p[t*4+1] = a.y; p[t*4+2] = a.z; p[t*4+3] = a.w;
                    }
                } else {
#pragma unroll
                    for (int t = 0; t < 16; t++) p[t] = 0.f;
                    p[0] = coord[(size_t)bs * 2];
                    p[1] = coord[(size_t)bs * 2 + 1];
                }
                uint32_t wv[8];
#pragma unroll
                for (int pp = 0; pp < 8; pp++) {
                    int kk = 2 * (pp >> 1) + 8 * (pp & 1);
                    wv[pp] = h2u(__floats2half2_rn(p[kk], p[kk + 1]));
                }
                u0 = make_uint4(wv[0], wv[1], wv[2], wv[3]);
                u1 = make_uint4(wv[4], wv[5], wv[6], wv[7]);
            }
            uint4* dst = (uint4*)(Xh32 + (size_t)bs * 144 + gp * 8);
            dst[0] = u0; dst[1] = u1;
        }
    } else {
        int wb = blk - 32;
        const float* gsrc; int rowoff, c, klim; __half* dstf;
        if (wb < 10)      { gsrc = gw1; rowoff = 0;   c = wb;      klim = KX;  dstf = d_WJf; }
        else if (wb < 20) { gsrc = gw1; rowoff = 258; c = wb - 10; klim = KX;  dstf = d_WIf; }
        else if (wb < 30) { gsrc = gw1; rowoff = 516; c = wb - 20; klim = KX;  dstf = d_W1f; }
        else if (wb < 38) { gsrc = gw2; rowoff = 0;   c = wb - 30; klim = 256; dstf = d_W2f; }
        else              { gsrc = gw3; rowoff = 0;   c = wb - 38; klim = 256; dstf = d_W3f; }

#pragma unroll 8
        for (int it = 0; it < 32; it++) {
            int s = tid + it * 256;
            int kk = s >> 8, n = s & 255;
            int k = c * 32 + kk;
            Ws[s] = (k < klim) ? gsrc[(size_t)(rowoff + k) * 256 + n] : 0.f;
        }
        __syncthreads();

        uint4* dst4 = (uint4*)(dstf + (size_t)c * 8192);
#pragma unroll
        for (int it = 0; it < 4; it++) {
            int seg = tid + it * 256;
            __half hv[8];
#pragma unroll
            for (int x = 0; x < 8; x++) {
                int e = seg * 8 + x;
                int off = e >> 1, h = e & 1;
                int ks = off >> 11, rem = off & 2047;
                int nb = rem >> 6, l2 = rem & 63;
                int lane = l2 >> 1, j = l2 & 1;
                int tg = lane & 3, g = lane >> 2;
                int kk = ks * 16 + j * 8 + 2 * tg + h;
                int n = nb * 8 + g;
                hv[x] = __float2half_rn(Ws[kk * 256 + n]);
            }
            uint4 u;
            u.x = h2u(__halves2half2(hv[0], hv[1]));
            u.y = h2u(__halves2half2(hv[2], hv[3]));
            u.z = h2u(__halves2half2(hv[4], hv[5]));
            u.w = h2u(__halves2half2(hv[6], hv[7]));
            dst4[seg] = u;
        }
    }
}

// ---------------- weight chunk staging (512 thr); IT*8 KB ----------------
template <int IT>
__device__ __forceinline__ void stage_chunk(uint32_t bdst, const __half* __restrict__ W) {
    int tid = threadIdx.x;
#pragma unroll
    for (int it = 0; it < IT; it++) {
        int seg = tid + it * 512;
        cpasync16(bdst + (uint32_t)seg * 16u, (const char*)W + (size_t)seg * 16);
    }
    asm volatile("cp.async.commit_group;");
}

// ---------------- fp16 fragment GEMM: 128x256, KC=64, 16 warps ---------------
// Last chunk runs only KS_LAST ks-steps (half-chunk peel for layer 1).
template <int NCH, int KS_LAST>
__device__ __forceinline__ void gemm_frag(
    float (&acc)[2][8][4],
    const uint32_t* __restrict__ Ap32,
    const uint32_t* __restrict__ wbuf, uint32_t wb_s32,
    const __half* __restrict__ W, int p0,
    const __half* __restrict__ nextW,
    int wm, int wn, int g, int tg)
{
#pragma unroll
    for (int mi = 0; mi < 2; mi++)
#pragma unroll
        for (int ni = 0; ni < 8; ni++)
#pragma unroll
            for (int q = 0; q < 4; q++) acc[mi][ni][q] = 0.f;

    int lane = threadIdx.x & 31;
    const uint32_t* A0 = Ap32 + (size_t)(wm * 32 + g) * ROW32 + 2 * tg;

    for (int c = 0; c < NCH - 1; c++) {
        asm volatile("cp.async.wait_group 0;" ::: "memory");
        __syncthreads();
        uint32_t nb = wb_s32 + (uint32_t)(((c + 1 + p0) & 1)) * 32768u;
        const __half* nw = W + (size_t)(c + 1) * 16384;
        if (KS_LAST == 2 && c + 2 == NCH) stage_chunk<2>(nb, nw);
        else                              stage_chunk<4>(nb, nw);
        const uint32_t* wb = wbuf + ((c + p0) & 1) * 8192;
#pragma unroll
        for (int ks = 0; ks < 4; ks++) {
            uint32_t a[2][4];
            const uint32_t* ar = A0 + c * 32 + ks * 8;
#pragma unroll
            for (int mi = 0; mi < 2; mi++) {
                uint2 L0 = *(const uint2*)(ar + (size_t)(mi * 16) * ROW32);
                uint2 L1 = *(const uint2*)(ar + (size_t)(mi * 16 + 8) * ROW32);
                a[mi][0] = L0.x; a[mi][1] = L1.x; a[mi][2] = L0.y; a[mi][3] = L1.y;
            }
            const uint32_t* wp = wb + ks * 2048 + wn * 512 + lane * 2;
#pragma unroll
            for (int ni = 0; ni < 8; ni++) {
                uint2 bb = *(const uint2*)(wp + ni * 64);
                uint32_t b[2] = {bb.x, bb.y};
                mma16(acc[0][ni], a[0], b);
                mma16(acc[1][ni], a[1], b);
            }
        }
    }
    // last chunk (KS_LAST ks-steps)
    {
        const int c = NCH - 1;
        asm volatile("cp.async.wait_group 0;" ::: "memory");
        __syncthreads();
        const uint32_t* wb = wbuf + ((c + p0) & 1) * 8192;
#pragma unroll
        for (int ks = 0; ks < KS_LAST; ks++) {
            uint32_t a[2][4];
            const uint32_t* ar = A0 + c * 32 + ks * 8;
#pragma unroll
            for (int mi = 0; mi < 2; mi++) {
                uint2 L0 = *(const uint2*)(ar + (size_t)(mi * 16) * ROW32);
                uint2 L1 = *(const uint2*)(ar + (size_t)(mi * 16 + 8) * ROW32);
                a[mi][0] = L0.x; a[mi][1] = L1.x; a[mi][2] = L0.y; a[mi][3] = L1.y;
            }
            const uint32_t* wp = wb + ks * 2048 + wn * 512 + lane * 2;
#pragma unroll
            for (int ni = 0; ni < 8; ni++) {
                uint2 bb = *(const uint2*)(wp + ni * 64);
                uint32_t b[2] = {bb.x, bb.y};
                mma16(acc[0][ni], a[0], b);
                mma16(acc[1][ni], a[1], b);
            }
        }
    }
    if (nextW)
        stage_chunk<4>(wb_s32 + (uint32_t)(((NCH + p0) & 1)) * 32768u, nextW);
}

// ---------------- kernel AJI: AJ/AI via tensor cores, 32 CTAs -----------------
__global__ void __launch_bounds__(512, 1) k_aji() {
    extern __shared__ char smc[];
    uint32_t* Ap32 = (uint32_t*)smc;
    uint32_t* wbuf = (uint32_t*)(smc + OFF_WB);

    int tid = threadIdx.x;
    int w = tid >> 5, lane = tid & 31;
    int wm = w >> 2, wn = w & 3;
    int g = lane >> 2, tg = lane & 3;
    int rb = blockIdx.x >> 1, half_ = blockIdx.x & 1;

    uint32_t a_s32  = (uint32_t)__cvta_generic_to_shared(Ap32);
    uint32_t wb_s32 = (uint32_t)__cvta_generic_to_shared(wbuf);
    const __half* Wf = half_ ? d_WIf : d_WJf;

    // A tile: 128 rows of d_Xh (576 B) into stride-672B rows (18 valid groups)
#pragma unroll 2
    for (int s = tid; s < 128 * 36; s += 512) {
        int row = s / 36, sg = s % 36;
        cpasync16(a_s32 + (uint32_t)(row * 672 + sg * 16),
                  (const char*)d_Xh + (size_t)(rb * 128 + row) * 576 + sg * 16);
    }
    stage_chunk<4>(wb_s32, Wf);

    float acc[2][8][4];
    gemm_frag<5, 2>(acc, Ap32, wbuf, wb_s32, Wf, 0, (const __half*)0, wm, wn, g, tg);

    float* dst = half_ ? d_AI : d_AJ;
#pragma unroll
    for (int mi = 0; mi < 2; mi++) {
        int r = wm * 32 + mi * 16 + g;
#pragma unroll
        for (int ni = 0; ni < 8; ni++) {
            int c0 = wn * 64 + ni * 8 + 2 * tg;
            *(float2*)(dst + (size_t)(rb * 128 + r) * H_ + c0) =
                make_float2(acc[mi][ni][0], acc[mi][ni][1]);
            *(float2*)(dst + (size_t)(rb * 128 + r + 8) * H_ + c0) =
                make_float2(acc[mi][ni][2], acc[mi][ni][3]);
        }
    }
}

// ---------------- kernel C: main fused chain, 512 thr, one CTA per (b,ipair) -
__global__ void __launch_bounds__(512, 1) k_main(
    const float* __restrict__ gb1, const float* __restrict__ gb2,
    const float* __restrict__ gb3)
{
    extern __shared__ char smc[];
    uint32_t* Ap32 = (uint32_t*)smc;
    uint32_t* wbuf = (uint32_t*)(smc + OFF_WB);
    float* xi_s = (float*)(smc + OFF_XI);
    float* aib0 = (float*)(smc + OFF_AIB0);
    float* aib1 = (float*)(smc + OFF_AIB1);
    float* b2s  = (float*)(smc + OFF_B2);
    float* b3s  = (float*)(smc + OFF_B3);

    int tid = threadIdx.x;
    int w = tid >> 5, lane = tid & 31;
    int wm = w >> 2, wn = w & 3;
    int g = lane >> 2, tg = lane & 3;
    int b = blockIdx.x >> 5, ip = blockIdx.x & 31;
    int i0 = 2 * ip, i1 = 2 * ip + 1;

    uint32_t wb_s32 = (uint32_t)__cvta_generic_to_shared(wbuf);
    const float* Xb = d_X + (size_t)b * S_ * SA;

    stage_chunk<4>(wb_s32, d_W1f);

    for (int k = tid; k < 2 * SA; k += 512) {
        int half_ = k >= SA, kk = k - half_ * SA;
        xi_s[k] = Xb[(size_t)(half_ ? i1 : i0) * SA + kk];
    }
    if (tid < 256) {
        aib0[tid] = d_AI[(size_t)(b * S_ + i0) * H_ + tid] + gb1[tid];
        aib1[tid] = d_AI[(size_t)(b * S_ + i1) * H_ + tid] + gb1[tid];
        b2s[tid] = gb2[tid];
        b3s[tid] = gb3[tid];
    }
    __syncthreads();

    // build P tile (half, k-permuted fragment layout), 128 rows x 20 groups
#pragma unroll 1
    for (int q = 0; q < 5; q++) {
        int e = tid + q * 512;              // exactly 2560
        int r = e / 20, gp = e % 20;
        int half_ = r >> 6, j = r & 63;
        uint4 u0 = make_uint4(0u, 0u, 0u, 0u), u1 = u0;
        if (gp < 17) {
            const float* xj = Xb + (size_t)j * SA + gp * 16;
            const float* xv = xi_s + half_ * SA + gp * 16;
            float p[16];
#pragma unroll
            for (int t = 0; t < 4; t++) {
                float4 a = *(const float4*)(xj + t * 4);
                float4 c = *(const float4*)(xv + t * 4);
                p[t*4+0] = a.x * c.x; p[t*4+1] = a.y * c.y;
                p[t*4+2] = a.z * c.z; p[t*4+3] = a.w * c.w;
            }
            uint32_t wv[8];
#pragma unroll
            for (int pp = 0; pp < 8; pp++) {
                int kk = 2 * (pp >> 1) + 8 * (pp & 1);
                wv[pp] = h2u(__floats2half2_rn(p[kk], p[kk + 1]));
            }
            u0 = make_uint4(wv[0], wv[1], wv[2], wv[3]);
            u1 = make_uint4(wv[4], wv[5], wv[6], wv[7]);
        }
        uint4* dst = (uint4*)(Ap32 + (size_t)r * ROW32 + gp * 8);
        dst[0] = u0; dst[1] = u1;
    }

    float acc[2][8][4];

    // ======== layer 1 (K = 288 effective: 4 full chunks + half chunk) ========
    gemm_frag<5, 2>(acc, Ap32, wbuf, wb_s32, d_W1f, 0, d_W2f, wm, wn, g, tg);
    __syncthreads();
    {
        const float* AJb = d_AJ + (size_t)(b * S_) * H_;
        const float* aibp = (wm >= 2) ? aib1 : aib0;
#pragma unroll
        for (int mi = 0; mi < 2; mi++) {
            int r = wm * 32 + mi * 16 + g;
            int j0 = r & 63;
            const float* AJ0 = AJb + (size_t)j0 * H_;
            const float* AJ1 = AJb + (size_t)(j0 + 8) * H_;
#pragma unroll
            for (int ni = 0; ni < 8; ni++) {
                int c0 = wn * 64 + ni * 8 + 2 * tg;
                float2 aj0 = *(const float2*)(AJ0 + c0);
                float2 aj1 = *(const float2*)(AJ1 + c0);
                float2 ab  = *(const float2*)(aibp + c0);
                float v00 = fmaxf(acc[mi][ni][0] + aj0.x + ab.x, 0.f);
                float v01 = fmaxf(acc[mi][ni][1] + aj0.y + ab.y, 0.f);
                float v10 = fmaxf(acc[mi][ni][2] + aj1.x + ab.x, 0.f);
                float v11 = fmaxf(acc[mi][ni][3] + aj1.y + ab.y, 0.f);
                uint32_t boff = (uint32_t)((wn * 4 + (ni >> 1)) * 8 + 2 * tg + (ni & 1));
                Ap32[(size_t)r * ROW32 + boff]       = h2u(__floats2half2_rn(v00, v01));
                Ap32[(size_t)(r + 8) * ROW32 + boff] = h2u(__floats2half2_rn(v10, v11));
            }
        }
    }

    // ======== layer 2 (4 chunks of 64) ========
    gemm_frag<4, 4>(acc, Ap32, wbuf, wb_s32, d_W2f, 1, d_W3f, wm, wn, g, tg);
    __syncthreads();
    {
#pragma unroll
        for (int mi = 0; mi < 2; mi++) {
            int r = wm * 32 + mi * 16 + g;
#pragma unroll
            for (int ni = 0; ni < 8; ni++) {
                int c0 = wn * 64 + ni * 8 + 2 * tg;
                float2 ab = *(const float2*)(b2s + c0);
                float v00 = fmaxf(acc[mi][ni][0] + ab.x, 0.f);
                float v01 = fmaxf(acc[mi][ni][1] + ab.y, 0.f);
                float v10 = fmaxf(acc[mi][ni][2] + ab.x, 0.f);
                float v11 = fmaxf(acc[mi][ni][3] + ab.y, 0.f);
                uint32_t boff = (uint32_t)((wn * 4 + (ni >> 1)) * 8 + 2 * tg + (ni & 1));
                Ap32[(size_t)r * ROW32 + boff]       = h2u(__floats2half2_rn(v00, v01));
                Ap32[(size_t)(r + 8) * ROW32 + boff] = h2u(__floats2half2_rn(v10, v11));
            }
        }
    }

    // ======== layer 3 + row reduction ========
    gemm_frag<4, 4>(acc, Ap32, wbuf, wb_s32, d_W3f, 1, (const __half*)0, wm, wn, g, tg);
    __syncthreads();
    {
#pragma unroll
        for (int mi = 0; mi < 2; mi++) {
            int r = wm * 32 + mi * 16 + g;
#pragma unroll
            for (int ni = 0; ni < 8; ni++) {
                int c0 = wn * 64 + ni * 8 + 2 * tg;
                float2 ab = *(const float2*)(b3s + c0);
                float v00 = fmaxf(acc[mi][ni][0] + ab.x, 0.f);
                float v01 = fmaxf(acc[mi][ni][1] + ab.y, 0.f);
                float v10 = fmaxf(acc[mi][ni][2] + ab.x, 0.f);
                float v11 = fmaxf(acc[mi][ni][3] + ab.y, 0.f);
                Ap32[(size_t)r * ROW32 + (c0 >> 1)]       = h2u(__floats2half2_rn(v00, v01));
                Ap32[(size_t)(r + 8) * ROW32 + (c0 >> 1)] = h2u(__floats2half2_rn(v10, v11));
            }
        }
        __syncthreads();
        const __half* Aph = (const __half*)smc;
        int t = tid & 255, h = tid >> 8;
        float s = 0.f;
#pragma unroll 8
        for (int rr = 0; rr < 64; rr++)
            s += __half2float(Aph[(size_t)(h * 64 + rr) * ROWH + t]);
        d_PART[(size_t)(b * S_ + (h ? i1 : i0)) * H_ + t] = s;
    }
}

// ---------------- k_mlp: PART reduction + final MLP, 512 thr, 3-buffer ring --
__device__ __forceinline__ void stage_mlp(uint32_t bdst, const float* __restrict__ W) {
    int tid = threadIdx.x;
#pragma unroll
    for (int it = 0; it < 4; it++) {
        int seg = tid + it * 512;
        cpasync16(bdst + (uint32_t)seg * 16u, W + (size_t)seg * 4);
    }
    asm volatile("cp.async.commit_group;");
}

__device__ __forceinline__ float mlp_layer(
    const float* __restrict__ wsm, uint32_t w_s32,
    const float* __restrict__ sin, const float* __restrict__ Wg,
    const float* __restrict__ nextW, int t, int h, int base)
{
    float a0 = 0.f, a1 = 0.f, a2 = 0.f, a3 = 0.f;
    for (int c = 0; c < 8; c++) {
        asm volatile("cp.async.wait_group 1;" ::: "memory");
        __syncthreads();
        int nxt = c + 2;
        if (nxt < 8)
            stage_mlp(w_s32 + (uint32_t)(((base + nxt) % 3) * 32768),
                      Wg + (size_t)nxt * 8192);
        else if (nextW)
            stage_mlp(w_s32 + (uint32_t)(((base + nxt) % 3) * 32768),
                      nextW + (size_t)(nxt - 8) * 8192);
        else
            asm volatile("cp.async.commit_group;");   // keep group count uniform
        const float* W = wsm + ((base + c) % 3) * 8192;
        const float* s = sin + c * 32 + h * 16;
        const float* Wt = W + (h * 16) * 256 + t;
#pragma unroll
        for (int kk = 0; kk < 16; kk += 4) {
            a0 += s[kk]     * Wt[(kk)     * 256];
            a1 += s[kk + 1] * Wt[(kk + 1) * 256];
            a2 += s[kk + 2] * Wt[(kk + 2) * 256];
            a3 += s[kk + 3] * Wt[(kk + 3) * 256];
        }
    }
    return (a0 + a1) + (a2 + a3);
}

__global__ void __launch_bounds__(512) k_mlp(
    const float* __restrict__ fw1, const float* __restrict__ fb1,
    const float* __restrict__ fw2, const float* __restrict__ fb2,
    const float* __restrict__ fw3, const float* __restrict__ fb3,
    float* __restrict__ out)
{
    extern __shared__ char smc[];
    float* wsm = (float*)smc;                 // 3 x 8192 floats
    float* s0  = (float*)(smc + 98304);
    float* s1  = s0 + 256;
    float* s2  = s1 + 256;
    float* pp  = s2 + 256;                    // 512 floats

    int b = blockIdx.x, tid = threadIdx.x;
    int t = tid & 255, h = tid >> 8;
    uint32_t w_s32 = (uint32_t)__cvta_generic_to_shared(wsm);

    // chunks 0,1 of fw1 in flight while we reduce PART
    stage_mlp(w_s32, fw1);
    stage_mlp(w_s32 + 32768u, fw1 + 8192);

    {
        const float* P = d_PART + (size_t)b * S_ * H_ + (size_t)(h * 32) * H_ + t;
        float s = 0.f;
#pragma unroll 8
        for (int i = 0; i < 32; i++) s += P[(size_t)i * H_];
        pp[tid] = s;
    }
    __syncthreads();
    if (h == 0) s0[t] = pp[t] + pp[t + 256];
    // visibility via mlp_layer's first wait+sync

    float r1 = mlp_layer(wsm, w_s32, s0, fw1, fw2, t, h, 0);
    pp[tid] = r1;
    __syncthreads();
    if (h == 0) s1[t] = fmaxf(pp[t] + pp[t + 256] + fb1[t], 0.f);

    float r2 = mlp_layer(wsm, w_s32, s1, fw2, (const float*)0, t, h, 8);
    pp[tid] = r2;
    __syncthreads();
    if (h == 0) s2[t] = fmaxf(pp[t] + pp[t + 256] + fb2[t], 0.f);
    __syncthreads();

    // layer 3: stage fw3 (2560 floats) into buffer 0
    asm volatile("cp.async.wait_group 0;" ::: "memory");
    for (int seg = tid; seg < 640; seg += 512)
        cpasync16(w_s32 + (uint32_t)seg * 16u, fw3 + (size_t)seg * 4);
    asm volatile("cp.async.commit_group;");
    asm volatile("cp.async.wait_group 0;" ::: "memory");
    __syncthreads();

    if (tid < 160) {
        int o = tid % 10, hh = tid / 10;
        float a = 0.f;
#pragma unroll
        for (int k = 0; k < 16; k++)
            a += s2[hh * 16 + k] * wsm[(hh * 16 + k) * 10 + o];
        pp[tid] = a;
    }
    __syncthreads();
    if (tid < OUT_) {
        float a = fb3[tid];
#pragma unroll
        for (int hh = 0; hh < 16; hh++) a += pp[hh * 10 + tid];
        out[b * OUT_ + tid] = a;
    }
}

// ---------------- launch ----------------
extern "C" void kernel_launch(void* const* d_in, const int* in_sizes, int n_in,
                              void* d_out, int out_size) {
    const float* sent  = (const float*)d_in[0];
    const float* coord = (const float*)d_in[1];
    const float* gw1   = (const float*)d_in[2];
    const float* gb1   = (const float*)d_in[3];
    const float* gw2   = (const float*)d_in[4];
    const float* gb2   = (const float*)d_in[5];
    const float* gw3   = (const float*)d_in[6];
    const float* gb3   = (const float*)d_in[7];
    const float* fw1   = (const float*)d_in[8];
    const float* fb1   = (const float*)d_in[9];
    const float* fw2   = (const float*)d_in[10];
    const float* fb2   = (const float*)d_in[11];
    const float* fw3   = (const float*)d_in[12];
    const float* fb3   = (const float*)d_in[13];
    float* out = (float*)d_out;

    k_prep<<<78, 256>>>(sent, coord, gw1, gw2, gw3);

    cudaFuncSetAttribute(k_aji, cudaFuncAttributeMaxDynamicSharedMemorySize,
                         SMEM_AJI);
    k_aji<<<32, 512, SMEM_AJI>>>();

    cudaFuncSetAttribute(k_main, cudaFuncAttributeMaxDynamicSharedMemorySize,
                         SMEM_BYTES);
    k_main<<<B_ * S_ / 2, 512, SMEM_BYTES>>>(gb1, gb2, gb3);

    cudaFuncSetAttribute(k_mlp, cudaFuncAttributeMaxDynamicSharedMemorySize,
                         SMEM_MLP);
    k_mlp<<<B_, 512, SMEM_MLP>>>(fw1, fb1, fw2, fb2, fw3, fb3, out);
}